// round 6
// baseline (speedup 1.0000x reference)
#include <cuda_runtime.h>
#include <cuda_bf16.h>
#include <cuda_pipeline.h>
#include <math.h>

#define NPTS   64              // interpolation intervals over s in [0, 10]
#define TAB_N  (NPTS + 4)      // 68: +1 guard below, +2 above (Catmull-Rom)
#define S_MAX  10.0f           // 1/sqrt(EPS2)
#define EPS2   0.01f
#define BLK    128
#define SPB    128             // samples per tile
#define TPW    2               // tiles per worker block
#define NTB    17              // table-builder blocks (17*4 warps = 68 points)

__device__ float g_table[TAB_N];
__device__ int   g_tab_count = 0;
__device__ int   g_tab_flag  = 0;
__device__ int   g_fin       = 0;

struct __align__(16) BuilderSmem {
    float chunk[32 * 129];      // one 32-row slice of W2, padded
    float wbuf[4][2][128];      // [warp][h1|u][j]
};
struct __align__(16) WorkerSmem {
    float buf[TPW][SPB * 18];   // double-buffered sample tiles
    float tab[TAB_N];
    float minv[3];
};
union __align__(16) SmemU { BuilderSmem b; WorkerSmem w; };

// Catmull-Rom lookup of g(s) from shared-memory table
__device__ __forceinline__ float lookup_g(const float* __restrict__ tab, float s)
{
    const float inv_h = (float)NPTS / S_MAX;
    const float u = s * inv_h;
    int i = (int)u;
    if (i > NPTS - 1) i = NPTS - 1;
    const float t  = u - (float)i;
    const float p0 = tab[i];
    const float p1 = tab[i + 1];
    const float p2 = tab[i + 2];
    const float p3 = tab[i + 3];
    return p1 + 0.5f * t * ((p2 - p0)
           + t * ((2.0f * p0 - 5.0f * p1 + 4.0f * p2 - p3)
           + t * (3.0f * (p1 - p2) + (p3 - p0))));
}

__global__ void __launch_bounds__(BLK) hnn_fused(
    const float* __restrict__ z,  const float* __restrict__ log_m,
    const float* __restrict__ W1, const float* __restrict__ b1,
    const float* __restrict__ W2, const float* __restrict__ b2,
    const float* __restrict__ W3,
    float* __restrict__ out, int B)
{
    __shared__ SmemU sm;
    const int tid = threadIdx.x;
    const int bid = blockIdx.x;

    if (bid < NTB) {
        // ================= table builder: one point per warp =================
        const int warp = tid >> 5, lane = tid & 31;
        const int pt = bid * 4 + warp;                 // 0..67
        const float hstep = S_MAX / (float)NPTS;
        const float s = (float)(pt - 1) * hstep;

        float* h1 = sm.b.wbuf[warp][0];
        float* uu = sm.b.wbuf[warp][1];
        // layer 1: h1 = silu(a1), u = W1 * silu'(a1)
        #pragma unroll
        for (int m = 0; m < 4; m++) {
            const int j = lane + 32 * m;
            const float w  = W1[j];
            const float a  = fmaf(w, s, b1[j]);
            const float sg = 1.0f / (1.0f + __expf(-a));
            h1[j] = a * sg;
            uu[j] = w * sg * (1.0f + a * (1.0f - sg));
        }

        // fused fwd+bwd over W2 in 4 chunks of 32 rows (lane <-> row in chunk)
        float acch[4], accu[4];
        const float4* W24 = (const float4*)W2;
        for (int c = 0; c < 4; c++) {
            __syncthreads();   // chunk buffer free / h1 visible (1st iter)
            for (int f = tid; f < 1024; f += BLK) {    // 32 rows x 32 float4
                const int row = f >> 5, col4 = f & 31;
                const float4 v = W24[(c * 32 + row) * 32 + col4];
                float* d = sm.b.chunk + row * 129 + col4 * 4;
                d[0] = v.x; d[1] = v.y; d[2] = v.z; d[3] = v.w;
            }
            __syncthreads();
            float ah = b2[c * 32 + lane], au = 0.0f;
            const float* wr = sm.b.chunk + lane * 129;
            #pragma unroll 4
            for (int j = 0; j < 128; j++) {
                const float wa = wr[j];
                ah = fmaf(wa, h1[j], ah);
                au = fmaf(wa, uu[j], au);
            }
            acch[c] = ah; accu[c] = au;
        }
        // tot = sum_k W3_k * silu'(a2_k) * (W2 @ u)_k
        float tot = 0.0f;
        #pragma unroll
        for (int c = 0; c < 4; c++) {
            const float a  = acch[c];
            const float sg = 1.0f / (1.0f + __expf(-a));
            tot = fmaf(W3[c * 32 + lane] * sg * (1.0f + a * (1.0f - sg)), accu[c], tot);
        }
        #pragma unroll
        for (int off = 16; off; off >>= 1)
            tot += __shfl_xor_sync(0xffffffffu, tot, off);
        if (lane == 0) g_table[pt] = tot;

        __syncthreads();
        if (tid == 0) {
            __threadfence();
            const int prev = atomicAdd(&g_tab_count, 1);
            if (prev == NTB - 1) {
                __threadfence();
                atomicExch(&g_tab_flag, 1);            // release table
            }
        }
    } else {
        // ========================= worker block =============================
        const int w = bid - NTB;
        const int ntiles = (B + SPB - 1) / SPB;
        const int t0 = w * TPW;

        // prefetch BOTH tiles (overlaps the table build)
        for (int t = 0; t < TPW; t++) {
            const int tile = t0 + t;
            if (tile < ntiles) {
                const int nelem = min(SPB, B - tile * SPB) * 18;
                const float* src = z + (size_t)tile * (SPB * 18);
                float* dst = sm.w.buf[t];
                const int n4 = nelem >> 2;
                for (int i = tid; i < n4; i += BLK)
                    __pipeline_memcpy_async(dst + 4 * i, src + 4 * i, 16);
                for (int i = (n4 << 2) + tid; i < nelem; i += BLK)
                    __pipeline_memcpy_async(dst + i, src + i, 4);
            }
            __pipeline_commit();
        }
        if (tid < 3) sm.w.minv[tid] = 1.0f / (expf(log_m[tid]) + 1e-8f);

        // leader waits for the table (exponential backoff, plain L2 poll)
        if (tid == 0) {
            unsigned ns = 64;
            while (*(volatile int*)&g_tab_flag == 0) {
                __nanosleep(ns);
                if (ns < 2048) ns <<= 1;
            }
        }
        __syncthreads();
        __threadfence();                   // acquire: table writes visible
        for (int i = tid; i < TAB_N; i += BLK) sm.w.tab[i] = g_table[i];
        __pipeline_wait_prior(0);          // both tiles landed
        __syncthreads();

        const float mi0 = sm.w.minv[0], mi1 = sm.w.minv[1], mi2 = sm.w.minv[2];

        for (int t = 0; t < TPW; t++) {
            const int tile = t0 + t;
            if (tile >= ntiles) break;
            const int nrows = min(SPB, B - tile * SPB);
            float* buf = sm.w.buf[t];

            if (tid < nrows) {
                float* r = buf + tid * 18;
                float q[9], p[9], f[9];
                #pragma unroll
                for (int c = 0; c < 9; c++) { q[c] = r[c]; p[c] = r[9 + c]; }
                #pragma unroll
                for (int c = 0; c < 3; c++) {
                    r[c]     = p[c]     * mi0;           // dq/dt
                    r[3 + c] = p[3 + c] * mi1;
                    r[6 + c] = p[6 + c] * mi2;
                }
                #pragma unroll
                for (int c = 0; c < 9; c++) f[c] = 0.0f;

                const int PI[3] = {0, 0, 1};
                const int PJ[3] = {1, 2, 2};
                #pragma unroll
                for (int pr = 0; pr < 3; pr++) {
                    const int bi = PI[pr] * 3, bj = PJ[pr] * 3;
                    const float dx = q[bi]     - q[bj];
                    const float dy = q[bi + 1] - q[bj + 1];
                    const float dz = q[bi + 2] - q[bj + 2];
                    const float r2 = fmaf(dx, dx, fmaf(dy, dy, fmaf(dz, dz, EPS2)));
                    const float s  = rsqrtf(r2);             // 1/d
                    const float g  = lookup_g(sm.w.tab, s);  // dV_pair/ds
                    const float wgt = g * s * s * s;         // g / d^3
                    f[bi]     += wgt * dx; f[bi + 1] += wgt * dy; f[bi + 2] += wgt * dz;
                    f[bj]     -= wgt * dx; f[bj + 1] -= wgt * dy; f[bj + 2] -= wgt * dz;
                }
                #pragma unroll
                for (int c = 0; c < 9; c++) r[9 + c] = f[c]; // dp/dt
            }
            __syncthreads();

            const int nelem = nrows * 18;
            const int n4 = nelem >> 2;
            float* dg = out + (size_t)tile * (SPB * 18);
            float4* o4 = (float4*)dg;
            const float4* s4 = (const float4*)buf;
            for (int i = tid; i < n4; i += BLK) o4[i] = s4[i];
            for (int i = (n4 << 2) + tid; i < nelem; i += BLK) dg[i] = buf[i];
        }
    }

    // ===== epilogue: last block resets flags (deterministic graph replays) ===
    __syncthreads();
    if (tid == 0) {
        __threadfence();
        const int prev = atomicAdd(&g_fin, 1);
        if (prev == (int)gridDim.x - 1) {
            *(volatile int*)&g_tab_flag  = 0;
            *(volatile int*)&g_tab_count = 0;
            __threadfence();
            atomicExch(&g_fin, 0);
        }
    }
}

extern "C" void kernel_launch(void* const* d_in, const int* in_sizes, int n_in,
                              void* d_out, int out_size)
{
    const float* z     = (const float*)d_in[0];
    const float* log_m = (const float*)d_in[1];
    const float* W1    = (const float*)d_in[2];
    const float* b1    = (const float*)d_in[3];
    const float* W2    = (const float*)d_in[4];
    const float* b2    = (const float*)d_in[5];
    const float* W3    = (const float*)d_in[6];
    // d_in[7] = b3 drops out of the gradient
    float* out = (float*)d_out;
    const int B = in_sizes[0] / 18;

    const int ntiles   = (B + SPB - 1) / SPB;            // 2048
    const int nworkers = (ntiles + TPW - 1) / TPW;       // 1024
    const int grid     = NTB + nworkers;                 // 1041 <= wave-1 capacity

    hnn_fused<<<grid, BLK>>>(z, log_m, W1, b1, W2, b2, W3, out, B);
}

// round 7
// speedup vs baseline: 1.3795x; 1.3795x over previous
#include <cuda_runtime.h>
#include <cuda_bf16.h>
#include <cuda_pipeline.h>
#include <math.h>

#define NPTS   64              // interpolation intervals over s in [0, 10]
#define TAB_N  (NPTS + 4)      // 68: +1 guard below, +2 above (Catmull-Rom)
#define S_MAX  10.0f           // 1/sqrt(EPS2)
#define EPS2   0.01f
#define BLK    128
#define SPB    128             // samples per tile
#define TILES  2               // tiles per worker block (both prefetched up front)

// g(s) = d(MLP)/ds at s_k = (k-1)*h, k = 0..NPTS+3
__device__ float g_table[TAB_N];
__device__ float minv_g[3];

// ---------------------------------------------------------------------------
// Kernel 1: build the 1-D derivative table. One point per warp.
// Fused forward+backward: tot = sum_k g2_k * (W2 @ u)_k with u_j = W1_j*silu'(a1_j)
// -> W2 traversed ONCE row-major with two accumulators per output row.
// ---------------------------------------------------------------------------
__global__ void build_table_kernel(const float* __restrict__ W1,
                                   const float* __restrict__ b1,
                                   const float* __restrict__ W2,
                                   const float* __restrict__ b2,
                                   const float* __restrict__ W3,
                                   const float* __restrict__ log_m)
{
    extern __shared__ float sm[];
    float* sW2  = sm;                       // [128][129]
    float* sbuf = sm + 128 * 129;           // per-warp: 128 h1 + 128 u

    const float4* W24 = (const float4*)W2;
    for (int idx = threadIdx.x; idx < 128 * 32; idx += blockDim.x) {
        const float4 v = W24[idx];
        float* d = sW2 + (idx >> 5) * 129 + ((idx & 31) << 2);
        d[0] = v.x; d[1] = v.y; d[2] = v.z; d[3] = v.w;
    }
    if (blockIdx.x == 0 && threadIdx.x < 3)
        minv_g[threadIdx.x] = 1.0f / (expf(log_m[threadIdx.x]) + 1e-8f);
    __syncthreads();

    const int warp = threadIdx.x >> 5;
    const int lane = threadIdx.x & 31;
    float* sh1 = sbuf + warp * 256;
    float* su  = sh1 + 128;

    const int nwarps = (blockDim.x >> 5) * gridDim.x;
    const int gw     = blockIdx.x * (blockDim.x >> 5) + warp;
    const float hstep = S_MAX / (float)NPTS;

    for (int pt = gw; pt < TAB_N; pt += nwarps) {
        const float s = (float)(pt - 1) * hstep;

        #pragma unroll
        for (int m = 0; m < 4; m++) {
            const int j = lane + 32 * m;
            const float w  = W1[j];
            const float a  = fmaf(w, s, b1[j]);
            const float sg = 1.0f / (1.0f + __expf(-a));
            sh1[j] = a * sg;
            su[j]  = w * sg * (1.0f + a * (1.0f - sg));
        }
        __syncwarp();

        float acch0 = b2[lane], acch1 = b2[lane + 32],
              acch2 = b2[lane + 64], acch3 = b2[lane + 96];
        float accu0 = 0.f, accu1 = 0.f, accu2 = 0.f, accu3 = 0.f;
        const float* w0 = sW2 + lane * 129;
        #pragma unroll 4
        for (int j = 0; j < 128; j++) {
            const float hj = sh1[j];
            const float uj = su[j];
            const float wa = w0[j];
            const float wb = w0[32 * 129 + j];
            const float wc = w0[64 * 129 + j];
            const float wd = w0[96 * 129 + j];
            acch0 = fmaf(wa, hj, acch0);  accu0 = fmaf(wa, uj, accu0);
            acch1 = fmaf(wb, hj, acch1);  accu1 = fmaf(wb, uj, accu1);
            acch2 = fmaf(wc, hj, acch2);  accu2 = fmaf(wc, uj, accu2);
            acch3 = fmaf(wd, hj, acch3);  accu3 = fmaf(wd, uj, accu3);
        }

        float tot = 0.0f;
        #pragma unroll
        for (int m = 0; m < 4; m++) {
            const float a  = (m == 0) ? acch0 : (m == 1) ? acch1 : (m == 2) ? acch2 : acch3;
            const float au = (m == 0) ? accu0 : (m == 1) ? accu1 : (m == 2) ? accu2 : accu3;
            const float sg = 1.0f / (1.0f + __expf(-a));
            tot = fmaf(W3[lane + 32 * m] * sg * (1.0f + a * (1.0f - sg)), au, tot);
        }
        #pragma unroll
        for (int off = 16; off; off >>= 1)
            tot += __shfl_xor_sync(0xffffffffu, tot, off);
        if (lane == 0) g_table[pt] = tot;
        __syncwarp();
    }
}

// Catmull-Rom lookup of g(s) from a shared-memory table
__device__ __forceinline__ float lookup_g(const float* __restrict__ tab, float s)
{
    const float inv_h = (float)NPTS / S_MAX;
    const float u = s * inv_h;
    int i = (int)u;
    if (i > NPTS - 1) i = NPTS - 1;
    const float t  = u - (float)i;
    const float p0 = tab[i];
    const float p1 = tab[i + 1];
    const float p2 = tab[i + 2];
    const float p3 = tab[i + 3];
    return p1 + 0.5f * t * ((p2 - p0)
           + t * ((2.0f * p0 - 5.0f * p1 + 4.0f * p2 - p3)
           + t * (3.0f * (p1 - p2) + (p3 - p0))));
}

// ---------------------------------------------------------------------------
// Kernel 2: grid 1024 (occ ~60%), each block prefetches BOTH its tiles with
// cp.async up front, computes both in ONE barrier phase, then stores both.
// Cross-block overlap + deep in-flight prefetch hides the L2/DRAM latency.
// ---------------------------------------------------------------------------
__global__ void __launch_bounds__(BLK) hnn_kernel(const float* __restrict__ z,
                                                  float* __restrict__ out, int B)
{
    __shared__ __align__(16) float sbuf[TILES][SPB * 18];  // 18432 B
    __shared__ __align__(16) float s_tab[TAB_N];
    __shared__ float s_minv[3];

    const int tid = threadIdx.x;
    const int ntiles_tot = (B + SPB - 1) / SPB;
    const int tile0 = blockIdx.x * TILES;

    // prefetch both tiles
    #pragma unroll
    for (int t = 0; t < TILES; t++) {
        const int tile = tile0 + t;
        if (tile < ntiles_tot) {
            const int nelem = min(SPB, B - tile * SPB) * 18;
            const float* src = z + (size_t)tile * (SPB * 18);
            float* dst = sbuf[t];
            const int n4 = nelem >> 2;
            for (int i = tid; i < n4; i += BLK)
                __pipeline_memcpy_async(dst + 4 * i, src + 4 * i, 16);
            for (int i = (n4 << 2) + tid; i < nelem; i += BLK)
                __pipeline_memcpy_async(dst + i, src + i, 4);
        }
    }
    __pipeline_commit();

    for (int i = tid; i < TAB_N; i += BLK) s_tab[i] = g_table[i];
    if (tid < 3) s_minv[tid] = minv_g[tid];

    __pipeline_wait_prior(0);
    __syncthreads();

    const float mi0 = s_minv[0], mi1 = s_minv[1], mi2 = s_minv[2];

    // compute both tiles in one barrier phase
    #pragma unroll
    for (int t = 0; t < TILES; t++) {
        const int tile = tile0 + t;
        if (tile >= ntiles_tot) break;
        const int nrows = min(SPB, B - tile * SPB);
        if (tid < nrows) {
            float* r = sbuf[t] + tid * 18;
            float q[9], p[9], f[9];
            #pragma unroll
            for (int c = 0; c < 9; c++) { q[c] = r[c]; p[c] = r[9 + c]; }
            #pragma unroll
            for (int c = 0; c < 3; c++) {
                r[c]     = p[c]     * mi0;      // dq/dt
                r[3 + c] = p[3 + c] * mi1;
                r[6 + c] = p[6 + c] * mi2;
            }
            #pragma unroll
            for (int c = 0; c < 9; c++) f[c] = 0.0f;

            const int PI[3] = {0, 0, 1};
            const int PJ[3] = {1, 2, 2};
            #pragma unroll
            for (int pr = 0; pr < 3; pr++) {
                const int bi = PI[pr] * 3, bj = PJ[pr] * 3;
                const float dx = q[bi]     - q[bj];
                const float dy = q[bi + 1] - q[bj + 1];
                const float dz = q[bi + 2] - q[bj + 2];
                const float r2 = fmaf(dx, dx, fmaf(dy, dy, fmaf(dz, dz, EPS2)));
                const float s  = rsqrtf(r2);            // 1/d
                const float g  = lookup_g(s_tab, s);    // dV_pair/ds
                const float w  = g * s * s * s;         // g / d^3
                f[bi]     += w * dx;  f[bi + 1] += w * dy;  f[bi + 2] += w * dz;
                f[bj]     -= w * dx;  f[bj + 1] -= w * dy;  f[bj + 2] -= w * dz;
            }
            #pragma unroll
            for (int c = 0; c < 9; c++) r[9 + c] = f[c];   // dp/dt
        }
    }
    __syncthreads();

    // store both tiles, fully coalesced
    #pragma unroll
    for (int t = 0; t < TILES; t++) {
        const int tile = tile0 + t;
        if (tile >= ntiles_tot) break;
        const int nelem = min(SPB, B - tile * SPB) * 18;
        const int n4 = nelem >> 2;
        float* dg = out + (size_t)tile * (SPB * 18);
        float4* o4 = (float4*)dg;
        const float4* s4 = (const float4*)sbuf[t];
        for (int i = tid; i < n4; i += BLK) o4[i] = s4[i];
        for (int i = (n4 << 2) + tid; i < nelem; i += BLK) dg[i] = sbuf[t][i];
    }
}

extern "C" void kernel_launch(void* const* d_in, const int* in_sizes, int n_in,
                              void* d_out, int out_size)
{
    const float* z     = (const float*)d_in[0];
    const float* log_m = (const float*)d_in[1];
    const float* W1    = (const float*)d_in[2];
    const float* b1    = (const float*)d_in[3];
    const float* W2    = (const float*)d_in[4];
    const float* b2    = (const float*)d_in[5];
    const float* W3    = (const float*)d_in[6];
    // d_in[7] = b3 drops out of the gradient
    float* out = (float*)d_out;
    const int B = in_sizes[0] / 18;

    const size_t smem = (128 * 129 + 8 * 256) * sizeof(float);  // 74240 B
    cudaFuncSetAttribute(build_table_kernel,
                         cudaFuncAttributeMaxDynamicSharedMemorySize, (int)smem);

    // 9 blocks x 8 warps = 72 warps >= 68 table points (one point each)
    build_table_kernel<<<9, 256, smem>>>(W1, b1, W2, b2, W3, log_m);

    const int ntiles = (B + SPB - 1) / SPB;              // 2048
    const int grid   = (ntiles + TILES - 1) / TILES;     // 1024
    hnn_kernel<<<grid, BLK>>>(z, out, B);
}

// round 8
// speedup vs baseline: 1.3821x; 1.0019x over previous
#include <cuda_runtime.h>
#include <cuda_bf16.h>
#include <cuda_pipeline.h>
#include <math.h>

#define NPTS   64              // interpolation intervals over s in [0, 10]
#define TAB_N  (NPTS + 4)      // 68: +1 guard below, +2 above (Catmull-Rom)
#define S_MAX  10.0f           // 1/sqrt(EPS2)
#define EPS2   0.01f
#define BLK    128
#define SPB    128             // samples per tile
#define TILES  2               // tiles per worker block (both prefetched up front)

// g(s) = d(MLP)/ds at s_k = (k-1)*h, k = 0..NPTS+3
__device__ float g_table[TAB_N];
__device__ float minv_g[3];

// ---------------------------------------------------------------------------
// Kernel 1 (PDL primary): build the 1-D derivative table. One point per warp.
// Triggers the secondary launch immediately at entry so hnn's prefetch
// overlaps the table build. Fused fwd+bwd: tot = sum_k g2_k * (W2 @ u)_k,
// u_j = W1_j * silu'(a1_j) -> ONE row-major pass over W2.
// ---------------------------------------------------------------------------
__global__ void build_table_kernel(const float* __restrict__ W1,
                                   const float* __restrict__ b1,
                                   const float* __restrict__ W2,
                                   const float* __restrict__ b2,
                                   const float* __restrict__ W3,
                                   const float* __restrict__ log_m)
{
    cudaTriggerProgrammaticLaunchCompletion();   // let hnn_kernel start now

    extern __shared__ float sm[];
    float* sW2  = sm;                       // [128][129]
    float* sbuf = sm + 128 * 129;           // per-warp: 128 h1 + 128 u

    const float4* W24 = (const float4*)W2;
    for (int idx = threadIdx.x; idx < 128 * 32; idx += blockDim.x) {
        const float4 v = W24[idx];
        float* d = sW2 + (idx >> 5) * 129 + ((idx & 31) << 2);
        d[0] = v.x; d[1] = v.y; d[2] = v.z; d[3] = v.w;
    }
    if (blockIdx.x == 0 && threadIdx.x < 3)
        minv_g[threadIdx.x] = 1.0f / (expf(log_m[threadIdx.x]) + 1e-8f);
    __syncthreads();

    const int warp = threadIdx.x >> 5;
    const int lane = threadIdx.x & 31;
    float* sh1 = sbuf + warp * 256;
    float* su  = sh1 + 128;

    const int nwarps = (blockDim.x >> 5) * gridDim.x;
    const int gw     = blockIdx.x * (blockDim.x >> 5) + warp;
    const float hstep = S_MAX / (float)NPTS;

    for (int pt = gw; pt < TAB_N; pt += nwarps) {
        const float s = (float)(pt - 1) * hstep;

        #pragma unroll
        for (int m = 0; m < 4; m++) {
            const int j = lane + 32 * m;
            const float w  = W1[j];
            const float a  = fmaf(w, s, b1[j]);
            const float sg = 1.0f / (1.0f + __expf(-a));
            sh1[j] = a * sg;
            su[j]  = w * sg * (1.0f + a * (1.0f - sg));
        }
        __syncwarp();

        float acch0 = b2[lane], acch1 = b2[lane + 32],
              acch2 = b2[lane + 64], acch3 = b2[lane + 96];
        float accu0 = 0.f, accu1 = 0.f, accu2 = 0.f, accu3 = 0.f;
        const float* w0 = sW2 + lane * 129;
        #pragma unroll 4
        for (int j = 0; j < 128; j++) {
            const float hj = sh1[j];
            const float uj = su[j];
            const float wa = w0[j];
            const float wb = w0[32 * 129 + j];
            const float wc = w0[64 * 129 + j];
            const float wd = w0[96 * 129 + j];
            acch0 = fmaf(wa, hj, acch0);  accu0 = fmaf(wa, uj, accu0);
            acch1 = fmaf(wb, hj, acch1);  accu1 = fmaf(wb, uj, accu1);
            acch2 = fmaf(wc, hj, acch2);  accu2 = fmaf(wc, uj, accu2);
            acch3 = fmaf(wd, hj, acch3);  accu3 = fmaf(wd, uj, accu3);
        }

        float tot = 0.0f;
        #pragma unroll
        for (int m = 0; m < 4; m++) {
            const float a  = (m == 0) ? acch0 : (m == 1) ? acch1 : (m == 2) ? acch2 : acch3;
            const float au = (m == 0) ? accu0 : (m == 1) ? accu1 : (m == 2) ? accu2 : accu3;
            const float sg = 1.0f / (1.0f + __expf(-a));
            tot = fmaf(W3[lane + 32 * m] * sg * (1.0f + a * (1.0f - sg)), au, tot);
        }
        #pragma unroll
        for (int off = 16; off; off >>= 1)
            tot += __shfl_xor_sync(0xffffffffu, tot, off);
        if (lane == 0) g_table[pt] = tot;
        __syncwarp();
    }
}

// Catmull-Rom lookup of g(s) from a shared-memory table
__device__ __forceinline__ float lookup_g(const float* __restrict__ tab, float s)
{
    const float inv_h = (float)NPTS / S_MAX;
    const float u = s * inv_h;
    int i = (int)u;
    if (i > NPTS - 1) i = NPTS - 1;
    const float t  = u - (float)i;
    const float p0 = tab[i];
    const float p1 = tab[i + 1];
    const float p2 = tab[i + 2];
    const float p3 = tab[i + 3];
    return p1 + 0.5f * t * ((p2 - p0)
           + t * ((2.0f * p0 - 5.0f * p1 + 4.0f * p2 - p3)
           + t * (3.0f * (p1 - p2) + (p3 - p0))));
}

// ---------------------------------------------------------------------------
// Kernel 2 (PDL secondary): prefetch z tiles FIRST (independent of table),
// then cudaGridDependencySynchronize() to wait for the table, then compute.
// ---------------------------------------------------------------------------
__global__ void __launch_bounds__(BLK) hnn_kernel(const float* __restrict__ z,
                                                  float* __restrict__ out, int B)
{
    __shared__ __align__(16) float sbuf[TILES][SPB * 18];  // 18432 B
    __shared__ __align__(16) float s_tab[TAB_N];
    __shared__ float s_minv[3];

    const int tid = threadIdx.x;
    const int ntiles_tot = (B + SPB - 1) / SPB;
    const int tile0 = blockIdx.x * TILES;

    // prefetch both tiles (independent of the primary kernel)
    #pragma unroll
    for (int t = 0; t < TILES; t++) {
        const int tile = tile0 + t;
        if (tile < ntiles_tot) {
            const int nelem = min(SPB, B - tile * SPB) * 18;
            const float* src = z + (size_t)tile * (SPB * 18);
            float* dst = sbuf[t];
            const int n4 = nelem >> 2;
            for (int i = tid; i < n4; i += BLK)
                __pipeline_memcpy_async(dst + 4 * i, src + 4 * i, 16);
            for (int i = (n4 << 2) + tid; i < nelem; i += BLK)
                __pipeline_memcpy_async(dst + i, src + i, 4);
        }
    }
    __pipeline_commit();

    // wait for the table-builder grid to complete (HW dependency)
    cudaGridDependencySynchronize();

    for (int i = tid; i < TAB_N; i += BLK) s_tab[i] = g_table[i];
    if (tid < 3) s_minv[tid] = minv_g[tid];

    __pipeline_wait_prior(0);
    __syncthreads();

    const float mi0 = s_minv[0], mi1 = s_minv[1], mi2 = s_minv[2];

    // compute both tiles in one barrier phase
    #pragma unroll
    for (int t = 0; t < TILES; t++) {
        const int tile = tile0 + t;
        if (tile >= ntiles_tot) break;
        const int nrows = min(SPB, B - tile * SPB);
        if (tid < nrows) {
            float* r = sbuf[t] + tid * 18;
            float q[9], p[9], f[9];
            #pragma unroll
            for (int c = 0; c < 9; c++) { q[c] = r[c]; p[c] = r[9 + c]; }
            #pragma unroll
            for (int c = 0; c < 3; c++) {
                r[c]     = p[c]     * mi0;      // dq/dt
                r[3 + c] = p[3 + c] * mi1;
                r[6 + c] = p[6 + c] * mi2;
            }
            #pragma unroll
            for (int c = 0; c < 9; c++) f[c] = 0.0f;

            const int PI[3] = {0, 0, 1};
            const int PJ[3] = {1, 2, 2};
            #pragma unroll
            for (int pr = 0; pr < 3; pr++) {
                const int bi = PI[pr] * 3, bj = PJ[pr] * 3;
                const float dx = q[bi]     - q[bj];
                const float dy = q[bi + 1] - q[bj + 1];
                const float dz = q[bi + 2] - q[bj + 2];
                const float r2 = fmaf(dx, dx, fmaf(dy, dy, fmaf(dz, dz, EPS2)));
                const float s  = rsqrtf(r2);            // 1/d
                const float g  = lookup_g(s_tab, s);    // dV_pair/ds
                const float w  = g * s * s * s;         // g / d^3
                f[bi]     += w * dx;  f[bi + 1] += w * dy;  f[bi + 2] += w * dz;
                f[bj]     -= w * dx;  f[bj + 1] -= w * dy;  f[bj + 2] -= w * dz;
            }
            #pragma unroll
            for (int c = 0; c < 9; c++) r[9 + c] = f[c];   // dp/dt
        }
    }
    __syncthreads();

    // store both tiles, fully coalesced
    #pragma unroll
    for (int t = 0; t < TILES; t++) {
        const int tile = tile0 + t;
        if (tile >= ntiles_tot) break;
        const int nelem = min(SPB, B - tile * SPB) * 18;
        const int n4 = nelem >> 2;
        float* dg = out + (size_t)tile * (SPB * 18);
        float4* o4 = (float4*)dg;
        const float4* s4 = (const float4*)sbuf[t];
        for (int i = tid; i < n4; i += BLK) o4[i] = s4[i];
        for (int i = (n4 << 2) + tid; i < nelem; i += BLK) dg[i] = sbuf[t][i];
    }
}

extern "C" void kernel_launch(void* const* d_in, const int* in_sizes, int n_in,
                              void* d_out, int out_size)
{
    const float* z     = (const float*)d_in[0];
    const float* log_m = (const float*)d_in[1];
    const float* W1    = (const float*)d_in[2];
    const float* b1    = (const float*)d_in[3];
    const float* W2    = (const float*)d_in[4];
    const float* b2    = (const float*)d_in[5];
    const float* W3    = (const float*)d_in[6];
    // d_in[7] = b3 drops out of the gradient
    float* out = (float*)d_out;
    const int B = in_sizes[0] / 18;

    const size_t smem = (128 * 129 + 8 * 256) * sizeof(float);  // 74240 B
    cudaFuncSetAttribute(build_table_kernel,
                         cudaFuncAttributeMaxDynamicSharedMemorySize, (int)smem);

    // primary: 9 blocks x 8 warps = 72 warps >= 68 table points
    build_table_kernel<<<9, 256, smem>>>(W1, b1, W2, b2, W3, log_m);

    // secondary with programmatic dependent launch: overlaps primary
    const int ntiles = (B + SPB - 1) / SPB;              // 2048
    const int grid   = (ntiles + TILES - 1) / TILES;     // 1024

    cudaLaunchAttribute attrs[1];
    attrs[0].id = cudaLaunchAttributeProgrammaticStreamSerialization;
    attrs[0].val.programmaticStreamSerializationAllowed = 1;

    cudaLaunchConfig_t cfg = {};
    cfg.gridDim  = dim3(grid, 1, 1);
    cfg.blockDim = dim3(BLK, 1, 1);
    cfg.dynamicSmemBytes = 0;
    cfg.stream = 0;
    cfg.attrs = attrs;
    cfg.numAttrs = 1;

    cudaLaunchKernelEx(&cfg, hnn_kernel, z, out, B);
}